// round 7
// baseline (speedup 1.0000x reference)
#include <cuda_runtime.h>
#include <cuda_fp16.h>
#include <cstdint>

// ============================================================================
// SubtractionGaussian: out[b,h,i,j] = ||q_i||^2 + ||k_j||^2 - 2 q_i . k_j
// B*H = 32, Lq = Lk = 2048, D = 64, fp32 in/out.
//
// R6: B-column permutation makes mma fragments store-dense -> register-only
//     epilogue (4x STG.128 per slab, no smem staging). K carries the -2 scale.
//
// Permutation (per 64-col warp span): fragment col c = 8*nn + 2*t + e holds
// global col g = 16*(nn>>1) + 4*t + 2*(nn&1) + e. Then lane t's fragment
// values for v = nn>>1 form float4s at global cols 16v+4t..+3.
// ============================================================================

#define LQ 2048
#define LK 2048
#define DDIM 64
#define TILE_M 128
#define TILE_N 128
#define THREADS 256

#define QROW 72        // halfs per Qs row (144B; 9 granules == 1 mod 8 -> ldmatrix conflict-free)
#define KROW 136       // halfs per Ks row (272B; 17 granules == 1 mod 8 -> conflict-free)

__device__ __forceinline__ void mma16816(float* d, const uint32_t* a,
                                         uint32_t b0, uint32_t b1) {
    asm volatile(
        "mma.sync.aligned.m16n8k16.row.col.f32.f16.f16.f32 "
        "{%0,%1,%2,%3}, {%4,%5,%6,%7}, {%8,%9}, {%0,%1,%2,%3};"
        : "+f"(d[0]), "+f"(d[1]), "+f"(d[2]), "+f"(d[3])
        : "r"(a[0]), "r"(a[1]), "r"(a[2]), "r"(a[3]), "r"(b0), "r"(b1));
}

__device__ __forceinline__ void ldmatrix_x4(uint32_t* r, uint32_t addr) {
    asm volatile("ldmatrix.sync.aligned.m8n8.x4.shared.b16 {%0,%1,%2,%3}, [%4];"
                 : "=r"(r[0]), "=r"(r[1]), "=r"(r[2]), "=r"(r[3]) : "r"(addr));
}

__device__ __forceinline__ void ldmatrix_x4_trans(uint32_t* r, uint32_t addr) {
    asm volatile("ldmatrix.sync.aligned.m8n8.x4.trans.shared.b16 {%0,%1,%2,%3}, [%4];"
                 : "=r"(r[0]), "=r"(r[1]), "=r"(r[2]), "=r"(r[3]) : "r"(addr));
}

__global__ void __launch_bounds__(THREADS, 2)
subgauss_kernel(const float* __restrict__ q,   // [BH, Lq, D]
                const float* __restrict__ k,   // [BH, D, Lk]
                float* __restrict__ out)       // [BH, Lq, Lk]
{
    __shared__ __align__(16) __half Qs[TILE_M][QROW];   // 18432 B
    __shared__ __align__(16) __half Ks[DDIM][KROW];     // 17408 B (permuted cols, holds -2k)
    __shared__ __align__(16) float q2s[TILE_M];
    __shared__ __align__(16) float k2s[TILE_N];         // GLOBAL col order
    __shared__ __align__(16) float kpart[8][TILE_N];    // 4096 B

    const int tid = threadIdx.x;
    const int lane = tid & 31;
    const int wid = tid >> 5;

    const int bh = blockIdx.z;
    const int i0 = blockIdx.y * TILE_M;
    const int j0 = blockIdx.x * TILE_N;

    // ---- Q load: 2 rows per warp-inst (16 lanes x float4, 512B contiguous). ----
    {
        const int hi = lane >> 4;          // 0/1 -> row parity
        const int seg2 = lane & 15;        // 16 lanes per row
#pragma unroll
        for (int p = 0; p < 8; p++) {
            const int r = wid * 2 + hi + p * 16;
            const float* qrow = q + ((size_t)bh * LQ + (size_t)(i0 + r)) * DDIM;
            float4 v = *reinterpret_cast<const float4*>(qrow + seg2 * 4);
            float s = v.x * v.x + v.y * v.y + v.z * v.z + v.w * v.w;
            s += __shfl_down_sync(0xffffffffu, s, 8, 16);
            s += __shfl_down_sync(0xffffffffu, s, 4, 16);
            s += __shfl_down_sync(0xffffffffu, s, 2, 16);
            s += __shfl_down_sync(0xffffffffu, s, 1, 16);
            if (seg2 == 0) q2s[r] = s;
            __half2 h01 = __floats2half2_rn(v.x, v.y);
            __half2 h23 = __floats2half2_rn(v.z, v.w);
            uint2 u;
            u.x = *reinterpret_cast<uint32_t*>(&h01);
            u.y = *reinterpret_cast<uint32_t*>(&h23);
            *reinterpret_cast<uint2*>(&Qs[r][seg2 * 4]) = u;
        }
    }

    // ---- K load: 1 c-row per warp-inst; store -2k at PERMUTED fragment cols.
    //      Lane's 4 global cols g0=4*lane..+3 land at two half2 slots:
    //      phys cA = 72*(lane>>4) + 16*((lane>>2)&3) + 2*(lane&3), cB = cA + 8.
    //      Banks: disjoint across lanes (72 halfs = 36 words == 4 mod 32) -> 1 phase each.
    {
        const int wn_l = lane >> 4;
        const int Ll = lane & 15;
        const int cA = 72 * wn_l + 16 * (Ll >> 2) + 2 * (Ll & 3);
        const int cB = cA + 8;
        const float* kb = k + (size_t)bh * DDIM * LK + (size_t)j0 + lane * 4;
        float4 ksum = make_float4(0.f, 0.f, 0.f, 0.f);
#pragma unroll
        for (int p = 0; p < 8; p++) {
            const int c = wid + p * 8;
            float4 v = *reinterpret_cast<const float4*>(kb + (size_t)c * LK);
            ksum.x += v.x * v.x; ksum.y += v.y * v.y;
            ksum.z += v.z * v.z; ksum.w += v.w * v.w;
            __half2 hA = __floats2half2_rn(-2.0f * v.x, -2.0f * v.y);
            __half2 hB = __floats2half2_rn(-2.0f * v.z, -2.0f * v.w);
            *reinterpret_cast<__half2*>(&Ks[c][cA]) = hA;
            *reinterpret_cast<__half2*>(&Ks[c][cB]) = hB;
        }
        *reinterpret_cast<float4*>(&kpart[wid][lane * 4]) = ksum;
    }
    __syncthreads();

    // ---- k2 reduce: 128 threads sum 8 warp-partials (exact fp32, global order). ----
    if (tid < TILE_N) {
        float s = 0.0f;
#pragma unroll
        for (int w = 0; w < 8; w++) s += kpart[w][tid];
        k2s[tid] = s;
    }

    // ---- Mainloop: warp (wm,wn) -> rows [wm*32,+32) x global cols [wn*64,+64). ----
    const int wm = wid & 3;
    const int wn = wid >> 2;
    const int mbase = wm * 32;
    const int nbase = wn * 64;        // global col base (k2s / out)
    const int npbase = wn * 72;       // physical half-col base in Ks
    const int g = lane >> 3;          // ldmatrix quadrant
    const int lr = lane & 7;          // ldmatrix row

    float acc[2][8][4];
#pragma unroll
    for (int mm = 0; mm < 2; mm++)
#pragma unroll
        for (int nn = 0; nn < 8; nn++)
#pragma unroll
            for (int r = 0; r < 4; r++)
                acc[mm][nn][r] = 0.0f;

#pragma unroll
    for (int ks = 0; ks < 4; ks++) {
        uint32_t A[2][4];
#pragma unroll
        for (int mm = 0; mm < 2; mm++) {
            uint32_t addr = (uint32_t)__cvta_generic_to_shared(
                &Qs[mbase + mm * 16 + (g & 1) * 8 + lr][ks * 16 + (g >> 1) * 8]);
            ldmatrix_x4(A[mm], addr);
        }
#pragma unroll
        for (int e = 0; e < 4; e++) {
            uint32_t B[4];
            uint32_t addr = (uint32_t)__cvta_generic_to_shared(
                &Ks[ks * 16 + (g & 1) * 8 + lr][npbase + e * 16 + (g >> 1) * 8]);
            ldmatrix_x4_trans(B, addr);
            mma16816(acc[0][2 * e],     A[0], B[0], B[1]);
            mma16816(acc[1][2 * e],     A[1], B[0], B[1]);
            mma16816(acc[0][2 * e + 1], A[0], B[2], B[3]);
            mma16816(acc[1][2 * e + 1], A[1], B[2], B[3]);
        }
    }

    // k2s written by tid<128 must be visible to all warps before epilogue reads.
    __syncthreads();

    // ---- Register-only epilogue: acc already holds -2*q.k in store-dense order.
    //      Lane (gq,tq): float4 v -> row (mbase+mm*16+h*8+gq), global cols 16v+4tq..+3.
    //      Per STG.128 inst: 8 rows x 64B contiguous -> 8 line-touches.
    {
        const int gq = lane >> 2;
        const int tq = lane & 3;
#pragma unroll
        for (int mm = 0; mm < 2; mm++) {
#pragma unroll
            for (int h = 0; h < 2; h++) {
                const int r = mbase + mm * 16 + h * 8 + gq;
                const float q2v = q2s[r];
                float* orow = out + ((size_t)bh * LQ + (size_t)(i0 + r)) * LK + j0 + nbase;
#pragma unroll
                for (int v = 0; v < 4; v++) {
                    float4 k2v = *reinterpret_cast<const float4*>(
                        &k2s[nbase + v * 16 + tq * 4]);
                    float4 o;
                    o.x = q2v + k2v.x + acc[mm][2 * v][2 * h];
                    o.y = q2v + k2v.y + acc[mm][2 * v][2 * h + 1];
                    o.z = q2v + k2v.z + acc[mm][2 * v + 1][2 * h];
                    o.w = q2v + k2v.w + acc[mm][2 * v + 1][2 * h + 1];
                    *reinterpret_cast<float4*>(orow + v * 16 + tq * 4) = o;
                }
            }
        }
    }
}

// ---------------- Launch ----------------

extern "C" void kernel_launch(void* const* d_in, const int* in_sizes, int n_in,
                              void* d_out, int out_size) {
    const float* q = (const float*)d_in[0];   // [4,8,2048,64]
    const float* k = (const float*)d_in[1];   // [4,8,64,2048]
    float* out = (float*)d_out;               // [4,8,2048,2048]
    (void)in_sizes; (void)n_in; (void)out_size;

    dim3 grid(LK / TILE_N, LQ / TILE_M, 32);  // 16 x 16 x 32
    subgauss_kernel<<<grid, THREADS>>>(q, k, out);
}

// round 8
// speedup vs baseline: 1.2525x; 1.2525x over previous
#include <cuda_runtime.h>
#include <cuda_fp16.h>
#include <cstdint>

// ============================================================================
// SubtractionGaussian: out[b,h,i,j] = ||q_i||^2 + ||k_j||^2 - 2 q_i . k_j
// B*H = 32, Lq = Lk = 2048, D = 64, fp32 in/out.
//
// R8 = R5 design (staged epilogue, 4-line STG.128) scaled to TILE_M=256,
//      512 threads. Per-warp code identical to the verified R5 kernel.
// R6/R7 lesson: register-only epilogues force 8-line/64B STG instructions
//      (within-inst replays) -> slower despite fewer bytes. Stage stays.
// ============================================================================

#define LQ 2048
#define LK 2048
#define DDIM 64
#define TILE_M 256
#define TILE_N 128
#define THREADS 512
#define NWARP 16

#define QROW 72        // halfs per Qs row (144B; 9 granules == 1 mod 8 -> ldmatrix conflict-free)
#define KROW 136       // halfs per Ks row (272B; 17 granules == 1 mod 8 -> conflict-free)
#define SSTRIDE 72     // floats per stage row

// dynamic smem layout (bytes)
#define OFF_QS    0                       // 256*72*2   = 36864 (re-used as epilogue stage)
#define OFF_KS    36864                   // 64*136*2   = 17408
#define OFF_Q2    54272                   // 256*4      = 1024
#define OFF_K2    55296                   // 128*4      = 512
#define OFF_KP    55808                   // 16*128*4   = 8192
#define SMEM_TOTAL 64000

__device__ __forceinline__ void mma16816(float* d, const uint32_t* a,
                                         uint32_t b0, uint32_t b1) {
    asm volatile(
        "mma.sync.aligned.m16n8k16.row.col.f32.f16.f16.f32 "
        "{%0,%1,%2,%3}, {%4,%5,%6,%7}, {%8,%9}, {%0,%1,%2,%3};"
        : "+f"(d[0]), "+f"(d[1]), "+f"(d[2]), "+f"(d[3])
        : "r"(a[0]), "r"(a[1]), "r"(a[2]), "r"(a[3]), "r"(b0), "r"(b1));
}

__device__ __forceinline__ void ldmatrix_x4(uint32_t* r, uint32_t addr) {
    asm volatile("ldmatrix.sync.aligned.m8n8.x4.shared.b16 {%0,%1,%2,%3}, [%4];"
                 : "=r"(r[0]), "=r"(r[1]), "=r"(r[2]), "=r"(r[3]) : "r"(addr));
}

__device__ __forceinline__ void ldmatrix_x4_trans(uint32_t* r, uint32_t addr) {
    asm volatile("ldmatrix.sync.aligned.m8n8.x4.trans.shared.b16 {%0,%1,%2,%3}, [%4];"
                 : "=r"(r[0]), "=r"(r[1]), "=r"(r[2]), "=r"(r[3]) : "r"(addr));
}

__global__ void __launch_bounds__(THREADS, 1)
subgauss_kernel(const float* __restrict__ q,   // [BH, Lq, D]
                const float* __restrict__ k,   // [BH, D, Lk]
                float* __restrict__ out)       // [BH, Lq, Lk]
{
    extern __shared__ __align__(16) char smem[];
    __half* Qs = reinterpret_cast<__half*>(smem + OFF_QS);     // [TILE_M][QROW]
    __half* Ks = reinterpret_cast<__half*>(smem + OFF_KS);     // [DDIM][KROW]
    float* q2s = reinterpret_cast<float*>(smem + OFF_Q2);      // [TILE_M]
    float* k2s = reinterpret_cast<float*>(smem + OFF_K2);      // [TILE_N]
    float* kpart = reinterpret_cast<float*>(smem + OFF_KP);    // [NWARP][TILE_N]

    const int tid = threadIdx.x;
    const int lane = tid & 31;
    const int wid = tid >> 5;

    const int bh = blockIdx.z;
    const int i0 = blockIdx.y * TILE_M;
    const int j0 = blockIdx.x * TILE_N;

    // ---- Q load: 2 rows per warp-inst (16 lanes x float4, 512B contiguous). ----
    {
        const int hi = lane >> 4;          // 0/1 -> row parity
        const int seg2 = lane & 15;        // 16 lanes per row
#pragma unroll
        for (int p = 0; p < 8; p++) {
            const int r = wid * 2 + hi + p * 32;
            const float* qrow = q + ((size_t)bh * LQ + (size_t)(i0 + r)) * DDIM;
            float4 v = *reinterpret_cast<const float4*>(qrow + seg2 * 4);
            float s = v.x * v.x + v.y * v.y + v.z * v.z + v.w * v.w;
            s += __shfl_down_sync(0xffffffffu, s, 8, 16);
            s += __shfl_down_sync(0xffffffffu, s, 4, 16);
            s += __shfl_down_sync(0xffffffffu, s, 2, 16);
            s += __shfl_down_sync(0xffffffffu, s, 1, 16);
            if (seg2 == 0) q2s[r] = s;
            __half2 h01 = __floats2half2_rn(v.x, v.y);
            __half2 h23 = __floats2half2_rn(v.z, v.w);
            uint2 u;
            u.x = *reinterpret_cast<uint32_t*>(&h01);
            u.y = *reinterpret_cast<uint32_t*>(&h23);
            *reinterpret_cast<uint2*>(&Qs[r * QROW + seg2 * 4]) = u;
        }
    }

    // ---- K load: 1 c-row per warp-inst; exact fp32 k2 partials for free. ----
    {
        const float* kb = k + (size_t)bh * DDIM * LK + (size_t)j0 + lane * 4;
        float4 ksum = make_float4(0.f, 0.f, 0.f, 0.f);
#pragma unroll
        for (int p = 0; p < 4; p++) {
            const int c = wid + p * NWARP;
            float4 v = *reinterpret_cast<const float4*>(kb + (size_t)c * LK);
            ksum.x += v.x * v.x; ksum.y += v.y * v.y;
            ksum.z += v.z * v.z; ksum.w += v.w * v.w;
            __half2 h01 = __floats2half2_rn(v.x, v.y);
            __half2 h23 = __floats2half2_rn(v.z, v.w);
            uint2 u;
            u.x = *reinterpret_cast<uint32_t*>(&h01);
            u.y = *reinterpret_cast<uint32_t*>(&h23);
            *reinterpret_cast<uint2*>(&Ks[c * KROW + lane * 4]) = u;
        }
        *reinterpret_cast<float4*>(&kpart[wid * TILE_N + lane * 4]) = ksum;
    }
    __syncthreads();

    // ---- k2 reduce: 128 threads sum 16 warp-partials (exact fp32). ----
    if (tid < TILE_N) {
        float s = 0.0f;
#pragma unroll
        for (int w = 0; w < NWARP; w++) s += kpart[w * TILE_N + tid];
        k2s[tid] = s;
    }

    // ---- Mainloop: warp (wm,wn) -> rows [wm*32,+32) x cols [wn*64,+64). ----
    const int wm = wid & 7;
    const int wn = wid >> 3;
    const int mbase = wm * 32;
    const int nbase = wn * 64;
    const int g = lane >> 3;      // ldmatrix quadrant
    const int lr = lane & 7;      // ldmatrix row

    float acc[2][8][4];
#pragma unroll
    for (int mm = 0; mm < 2; mm++)
#pragma unroll
        for (int nn = 0; nn < 8; nn++)
#pragma unroll
            for (int r = 0; r < 4; r++)
                acc[mm][nn][r] = 0.0f;

#pragma unroll
    for (int ks = 0; ks < 4; ks++) {
        uint32_t A[2][4];
#pragma unroll
        for (int mm = 0; mm < 2; mm++) {
            uint32_t addr = (uint32_t)__cvta_generic_to_shared(
                &Qs[(mbase + mm * 16 + (g & 1) * 8 + lr) * QROW + ks * 16 + (g >> 1) * 8]);
            ldmatrix_x4(A[mm], addr);
        }
#pragma unroll
        for (int e = 0; e < 4; e++) {
            uint32_t B[4];
            uint32_t addr = (uint32_t)__cvta_generic_to_shared(
                &Ks[(ks * 16 + (g & 1) * 8 + lr) * KROW + nbase + e * 16 + (g >> 1) * 8]);
            ldmatrix_x4_trans(B, addr);
            mma16816(acc[0][2 * e],     A[0], B[0], B[1]);
            mma16816(acc[1][2 * e],     A[1], B[0], B[1]);
            mma16816(acc[0][2 * e + 1], A[0], B[2], B[3]);
            mma16816(acc[1][2 * e + 1], A[1], B[2], B[3]);
        }
    }

    // ---- All warps done with Qs/Ks; re-use Qs as per-warp stage buffers. ----
    __syncthreads();

    {
        float* stg = reinterpret_cast<float*>(Qs) + wid * 8 * SSTRIDE;
        const int gq = lane >> 2;      // source row within slab
        const int tq = lane & 3;       // source col pair
        const int rr = lane >> 3;      // dest row within 4-row group
        const int cc = lane & 7;       // dest 16B chunk

        // preload k2 (fixed per lane) and q2 (8 rows per lane)
        float4 k2A = *reinterpret_cast<const float4*>(&k2s[nbase + cc * 4]);
        float4 k2B = *reinterpret_cast<const float4*>(&k2s[nbase + 32 + cc * 4]);
        float q2r[8];
#pragma unroll
        for (int mm = 0; mm < 2; mm++)
#pragma unroll
            for (int h = 0; h < 2; h++)
#pragma unroll
                for (int G = 0; G < 2; G++)
                    q2r[mm * 4 + h * 2 + G] = q2s[mbase + mm * 16 + h * 8 + G * 4 + rr];

#pragma unroll
        for (int mm = 0; mm < 2; mm++) {
#pragma unroll
            for (int h = 0; h < 2; h++) {
                __syncwarp();
                // scatter-free STS: rows gq, float2 per (nn,tq)
#pragma unroll
                for (int nn = 0; nn < 8; nn++) {
                    float2 f2;
                    f2.x = acc[mm][nn][2 * h];
                    f2.y = acc[mm][nn][2 * h + 1];
                    *reinterpret_cast<float2*>(&stg[gq * SSTRIDE + nn * 8 + tq * 2]) = f2;
                }
                __syncwarp();
                // coalesced LDS.128 + math + dense STG.128 (4 rows x 128B per inst)
#pragma unroll
                for (int s = 0; s < 4; s++) {
                    const int G = s >> 1;
                    const int C = s & 1;
                    float4 x = *reinterpret_cast<const float4*>(
                        &stg[(G * 4 + rr) * SSTRIDE + C * 32 + cc * 4]);
                    const float q2v = q2r[mm * 4 + h * 2 + G];
                    const float4 k2v = C ? k2B : k2A;
                    float4 o;
                    o.x = q2v + k2v.x - 2.0f * x.x;
                    o.y = q2v + k2v.y - 2.0f * x.y;
                    o.z = q2v + k2v.z - 2.0f * x.z;
                    o.w = q2v + k2v.w - 2.0f * x.w;
                    float* dst = out + ((size_t)bh * LQ +
                                        (size_t)(i0 + mbase + mm * 16 + h * 8 + G * 4 + rr)) * LK
                                     + j0 + nbase + C * 32 + cc * 4;
                    *reinterpret_cast<float4*>(dst) = o;
                }
            }
        }
    }
}

// ---------------- Launch ----------------

extern "C" void kernel_launch(void* const* d_in, const int* in_sizes, int n_in,
                              void* d_out, int out_size) {
    const float* q = (const float*)d_in[0];   // [4,8,2048,64]
    const float* k = (const float*)d_in[1];   // [4,8,64,2048]
    float* out = (float*)d_out;               // [4,8,2048,2048]
    (void)in_sizes; (void)n_in; (void)out_size;

    cudaFuncSetAttribute(subgauss_kernel,
                         cudaFuncAttributeMaxDynamicSharedMemorySize, SMEM_TOTAL);

    dim3 grid(LK / TILE_N, LQ / TILE_M, 32);  // 16 x 8 x 32
    subgauss_kernel<<<grid, THREADS, SMEM_TOTAL>>>(q, k, out);
}

// round 9
// speedup vs baseline: 1.6481x; 1.3158x over previous
#include <cuda_runtime.h>
#include <cuda_fp16.h>
#include <cstdint>

// ============================================================================
// SubtractionGaussian: out[b,h,i,j] = ||q_i||^2 + ||k_j||^2 - 2 q_i . k_j
// B*H = 32, Lq = Lk = 2048, D = 64, fp32 in/out.
//
// R9: 256-thread CTA owns 256x256 output (2x2 sub-tiles of 128x128).
//     Q/K loaded+converted once, reused by 4 barrier-free tile iterations
//     (stage buffer is separate from Qs -> no CTA syncs after load phase).
//     Per-warp mainloop/epilogue identical to verified R5.
// ============================================================================

#define LQ 2048
#define LK 2048
#define DDIM 64
#define TM 256          // CTA rows
#define TN 256          // CTA cols
#define SUB 128         // sub-tile edge
#define THREADS 256

#define QROW 72         // halfs per Qs row (9 granules == 1 mod 8 -> ldmatrix conflict-free)
#define KROW 264        // halfs per Ks row (33 granules == 1 mod 8 -> conflict-free)
#define SSTRIDE 72      // floats per stage row

// dynamic smem layout (bytes)
#define OFF_QS   0                        // 256*72*2  = 36864
#define OFF_KS   36864                    // 64*264*2  = 33792
#define OFF_STG  70656                    // 8*8*72*4  = 18432
#define OFF_Q2   89088                    // 256*4     = 1024
#define OFF_K2   90112                    // 256*4     = 1024
#define OFF_KP   91136                    // 8*256*4   = 8192
#define SMEM_TOTAL 99328

__device__ __forceinline__ void mma16816(float* d, const uint32_t* a,
                                         uint32_t b0, uint32_t b1) {
    asm volatile(
        "mma.sync.aligned.m16n8k16.row.col.f32.f16.f16.f32 "
        "{%0,%1,%2,%3}, {%4,%5,%6,%7}, {%8,%9}, {%0,%1,%2,%3};"
        : "+f"(d[0]), "+f"(d[1]), "+f"(d[2]), "+f"(d[3])
        : "r"(a[0]), "r"(a[1]), "r"(a[2]), "r"(a[3]), "r"(b0), "r"(b1));
}

__device__ __forceinline__ void ldmatrix_x4(uint32_t* r, uint32_t addr) {
    asm volatile("ldmatrix.sync.aligned.m8n8.x4.shared.b16 {%0,%1,%2,%3}, [%4];"
                 : "=r"(r[0]), "=r"(r[1]), "=r"(r[2]), "=r"(r[3]) : "r"(addr));
}

__device__ __forceinline__ void ldmatrix_x4_trans(uint32_t* r, uint32_t addr) {
    asm volatile("ldmatrix.sync.aligned.m8n8.x4.trans.shared.b16 {%0,%1,%2,%3}, [%4];"
                 : "=r"(r[0]), "=r"(r[1]), "=r"(r[2]), "=r"(r[3]) : "r"(addr));
}

__global__ void __launch_bounds__(THREADS, 2)
subgauss_kernel(const float* __restrict__ q,   // [BH, Lq, D]
                const float* __restrict__ k,   // [BH, D, Lk]
                float* __restrict__ out)       // [BH, Lq, Lk]
{
    extern __shared__ __align__(16) char smem[];
    __half* Qs = reinterpret_cast<__half*>(smem + OFF_QS);     // [TM][QROW]
    __half* Ks = reinterpret_cast<__half*>(smem + OFF_KS);     // [DDIM][KROW]
    float* stgall = reinterpret_cast<float*>(smem + OFF_STG);  // [8][8*SSTRIDE]
    float* q2s = reinterpret_cast<float*>(smem + OFF_Q2);      // [TM]
    float* k2s = reinterpret_cast<float*>(smem + OFF_K2);      // [TN]
    float* kpart = reinterpret_cast<float*>(smem + OFF_KP);    // [8][TN]

    const int tid = threadIdx.x;
    const int lane = tid & 31;
    const int wid = tid >> 5;

    const int bh = blockIdx.z;
    const int i0 = blockIdx.y * TM;
    const int j0 = blockIdx.x * TN;

    // ---- Q load: 256 rows; 2 rows per warp-inst (16 lanes x float4). ----
    {
        const int hi = lane >> 4;
        const int seg2 = lane & 15;
#pragma unroll
        for (int p = 0; p < 16; p++) {
            const int r = wid * 2 + hi + p * 16;
            const float* qrow = q + ((size_t)bh * LQ + (size_t)(i0 + r)) * DDIM;
            float4 v = *reinterpret_cast<const float4*>(qrow + seg2 * 4);
            float s = v.x * v.x + v.y * v.y + v.z * v.z + v.w * v.w;
            s += __shfl_down_sync(0xffffffffu, s, 8, 16);
            s += __shfl_down_sync(0xffffffffu, s, 4, 16);
            s += __shfl_down_sync(0xffffffffu, s, 2, 16);
            s += __shfl_down_sync(0xffffffffu, s, 1, 16);
            if (seg2 == 0) q2s[r] = s;
            __half2 h01 = __floats2half2_rn(v.x, v.y);
            __half2 h23 = __floats2half2_rn(v.z, v.w);
            uint2 u;
            u.x = *reinterpret_cast<uint32_t*>(&h01);
            u.y = *reinterpret_cast<uint32_t*>(&h23);
            *reinterpret_cast<uint2*>(&Qs[r * QROW + seg2 * 4]) = u;
        }
    }

    // ---- K load: 256 cols (two 128-col halves); exact fp32 k2 partials. ----
#pragma unroll
    for (int jt = 0; jt < 2; jt++) {
        const float* kb = k + (size_t)bh * DDIM * LK + (size_t)(j0 + jt * SUB) + lane * 4;
        float4 ksum = make_float4(0.f, 0.f, 0.f, 0.f);
#pragma unroll
        for (int p = 0; p < 8; p++) {
            const int c = wid + p * 8;
            float4 v = *reinterpret_cast<const float4*>(kb + (size_t)c * LK);
            ksum.x += v.x * v.x; ksum.y += v.y * v.y;
            ksum.z += v.z * v.z; ksum.w += v.w * v.w;
            __half2 h01 = __floats2half2_rn(v.x, v.y);
            __half2 h23 = __floats2half2_rn(v.z, v.w);
            uint2 u;
            u.x = *reinterpret_cast<uint32_t*>(&h01);
            u.y = *reinterpret_cast<uint32_t*>(&h23);
            *reinterpret_cast<uint2*>(&Ks[c * KROW + jt * SUB + lane * 4]) = u;
        }
        *reinterpret_cast<float4*>(&kpart[wid * TN + jt * SUB + lane * 4]) = ksum;
    }
    __syncthreads();

    // ---- k2 reduce: all 256 threads, exact fp32. ----
    {
        float s = 0.0f;
#pragma unroll
        for (int w = 0; w < 8; w++) s += kpart[w * TN + tid];
        k2s[tid] = s;
    }
    __syncthreads();
    // -------- no CTA-wide barriers below this line --------

    const int wm = wid & 3;
    const int wn = wid >> 2;
    const int mbase = wm * 32;
    const int nbase = wn * 64;
    const int g = lane >> 3;      // ldmatrix quadrant
    const int lr = lane & 7;      // ldmatrix row

    float* stg = stgall + wid * 8 * SSTRIDE;   // warp-private stage
    const int gq = lane >> 2;
    const int tq = lane & 3;
    const int rr = lane >> 3;
    const int cc = lane & 7;

#pragma unroll 1
    for (int it = 0; it < 2; it++) {
#pragma unroll 1
        for (int jt = 0; jt < 2; jt++) {
            float acc[2][8][4];
#pragma unroll
            for (int mm = 0; mm < 2; mm++)
#pragma unroll
                for (int nn = 0; nn < 8; nn++)
#pragma unroll
                    for (int r = 0; r < 4; r++)
                        acc[mm][nn][r] = 0.0f;

            // ---- Mainloop (identical per-warp structure to R5). ----
#pragma unroll
            for (int ks = 0; ks < 4; ks++) {
                uint32_t A[2][4];
#pragma unroll
                for (int mm = 0; mm < 2; mm++) {
                    uint32_t addr = (uint32_t)__cvta_generic_to_shared(
                        &Qs[(it * SUB + mbase + mm * 16 + (g & 1) * 8 + lr) * QROW
                            + ks * 16 + (g >> 1) * 8]);
                    ldmatrix_x4(A[mm], addr);
                }
#pragma unroll
                for (int e = 0; e < 4; e++) {
                    uint32_t B[4];
                    uint32_t addr = (uint32_t)__cvta_generic_to_shared(
                        &Ks[(ks * 16 + (g & 1) * 8 + lr) * KROW
                            + jt * SUB + nbase + e * 16 + (g >> 1) * 8]);
                    ldmatrix_x4_trans(B, addr);
                    mma16816(acc[0][2 * e],     A[0], B[0], B[1]);
                    mma16816(acc[1][2 * e],     A[1], B[0], B[1]);
                    mma16816(acc[0][2 * e + 1], A[0], B[2], B[3]);
                    mma16816(acc[1][2 * e + 1], A[1], B[2], B[3]);
                }
            }

            // ---- Staged epilogue (R5 pattern, warp-private stage). ----
            float4 k2A = *reinterpret_cast<const float4*>(
                &k2s[jt * SUB + nbase + cc * 4]);
            float4 k2B = *reinterpret_cast<const float4*>(
                &k2s[jt * SUB + nbase + 32 + cc * 4]);
            float q2r[8];
#pragma unroll
            for (int mm = 0; mm < 2; mm++)
#pragma unroll
                for (int h = 0; h < 2; h++)
#pragma unroll
                    for (int G = 0; G < 2; G++)
                        q2r[mm * 4 + h * 2 + G] =
                            q2s[it * SUB + mbase + mm * 16 + h * 8 + G * 4 + rr];

#pragma unroll
            for (int mm = 0; mm < 2; mm++) {
#pragma unroll
                for (int h = 0; h < 2; h++) {
                    __syncwarp();
#pragma unroll
                    for (int nn = 0; nn < 8; nn++) {
                        float2 f2;
                        f2.x = acc[mm][nn][2 * h];
                        f2.y = acc[mm][nn][2 * h + 1];
                        *reinterpret_cast<float2*>(
                            &stg[gq * SSTRIDE + nn * 8 + tq * 2]) = f2;
                    }
                    __syncwarp();
#pragma unroll
                    for (int s = 0; s < 4; s++) {
                        const int G = s >> 1;
                        const int C = s & 1;
                        float4 x = *reinterpret_cast<const float4*>(
                            &stg[(G * 4 + rr) * SSTRIDE + C * 32 + cc * 4]);
                        const float q2v = q2r[mm * 4 + h * 2 + G];
                        const float4 k2v = C ? k2B : k2A;
                        float4 o;
                        o.x = q2v + k2v.x - 2.0f * x.x;
                        o.y = q2v + k2v.y - 2.0f * x.y;
                        o.z = q2v + k2v.z - 2.0f * x.z;
                        o.w = q2v + k2v.w - 2.0f * x.w;
                        float* dst = out + ((size_t)bh * LQ +
                            (size_t)(i0 + it * SUB + mbase + mm * 16 + h * 8 + G * 4 + rr)) * LK
                            + j0 + jt * SUB + nbase + C * 32 + cc * 4;
                        *reinterpret_cast<float4*>(dst) = o;
                    }
                }
            }
        }
    }
}

// ---------------- Launch ----------------

extern "C" void kernel_launch(void* const* d_in, const int* in_sizes, int n_in,
                              void* d_out, int out_size) {
    const float* q = (const float*)d_in[0];   // [4,8,2048,64]
    const float* k = (const float*)d_in[1];   // [4,8,64,2048]
    float* out = (float*)d_out;               // [4,8,2048,2048]
    (void)in_sizes; (void)n_in; (void)out_size;

    cudaFuncSetAttribute(subgauss_kernel,
                         cudaFuncAttributeMaxDynamicSharedMemorySize, SMEM_TOTAL);

    dim3 grid(LK / TN, LQ / TM, 32);  // 8 x 8 x 32
    subgauss_kernel<<<grid, THREADS, SMEM_TOTAL>>>(q, k, out);
}

// round 10
// speedup vs baseline: 1.6960x; 1.0291x over previous
#include <cuda_runtime.h>
#include <cuda_fp16.h>
#include <cstdint>

// ============================================================================
// SubtractionGaussian: out[b,h,i,j] = ||q_i||^2 + ||k_j||^2 - 2 q_i . k_j
// B*H = 32, Lq = Lk = 2048, D = 64, fp32 in/out.
//
// R10 = R9 (256x256 CTA, barrier-free 4-tile loop) + fp16 interleaved stage:
//   - stage holds -2*qk as fp16, row-pair interleaved (super-row s = rows 2s,2s+1,
//     word c = half2(rowEven col c, rowOdd col c), pitch 72 words)
//   - writer: 1 shfl.xor(4) + merge per nn, STS.32 conflict-free
//   - reader: 2x LDS.128 (conflict-free) -> cvt -> 4x STG.128, 4 rows x 128B dense
//   Epilogue phases/slab: 48 -> ~40 (32 if shfl off the l1tex path).
// ============================================================================

#define LQ 2048
#define LK 2048
#define DDIM 64
#define TM 256
#define TN 256
#define SUB 128
#define THREADS 256

#define QROW 72         // halfs per Qs row (9 granules == 1 mod 8 -> ldmatrix conflict-free)
#define KROW 264        // halfs per Ks row (33 granules == 1 mod 8 -> conflict-free)
#define SWORDS 72       // stage super-row pitch in words (== 8 mod 32 -> STS conflict-free)

// dynamic smem layout (bytes)
#define OFF_QS   0                        // 256*72*2  = 36864
#define OFF_KS   36864                    // 64*264*2  = 33792
#define OFF_STG  70656                    // 8 warps * 4*72*4 = 9216
#define OFF_Q2   79872                    // 256*4     = 1024
#define OFF_K2   80896                    // 256*4     = 1024
#define OFF_KP   81920                    // 8*256*4   = 8192
#define SMEM_TOTAL 90112

__device__ __forceinline__ void mma16816(float* d, const uint32_t* a,
                                         uint32_t b0, uint32_t b1) {
    asm volatile(
        "mma.sync.aligned.m16n8k16.row.col.f32.f16.f16.f32 "
        "{%0,%1,%2,%3}, {%4,%5,%6,%7}, {%8,%9}, {%0,%1,%2,%3};"
        : "+f"(d[0]), "+f"(d[1]), "+f"(d[2]), "+f"(d[3])
        : "r"(a[0]), "r"(a[1]), "r"(a[2]), "r"(a[3]), "r"(b0), "r"(b1));
}

__device__ __forceinline__ void ldmatrix_x4(uint32_t* r, uint32_t addr) {
    asm volatile("ldmatrix.sync.aligned.m8n8.x4.shared.b16 {%0,%1,%2,%3}, [%4];"
                 : "=r"(r[0]), "=r"(r[1]), "=r"(r[2]), "=r"(r[3]) : "r"(addr));
}

__device__ __forceinline__ void ldmatrix_x4_trans(uint32_t* r, uint32_t addr) {
    asm volatile("ldmatrix.sync.aligned.m8n8.x4.trans.shared.b16 {%0,%1,%2,%3}, [%4];"
                 : "=r"(r[0]), "=r"(r[1]), "=r"(r[2]), "=r"(r[3]) : "r"(addr));
}

__global__ void __launch_bounds__(THREADS, 2)
subgauss_kernel(const float* __restrict__ q,   // [BH, Lq, D]
                const float* __restrict__ k,   // [BH, D, Lk]
                float* __restrict__ out)       // [BH, Lq, Lk]
{
    extern __shared__ __align__(16) char smem[];
    __half* Qs = reinterpret_cast<__half*>(smem + OFF_QS);       // [TM][QROW]
    __half* Ks = reinterpret_cast<__half*>(smem + OFF_KS);       // [DDIM][KROW]
    uint32_t* stgall = reinterpret_cast<uint32_t*>(smem + OFF_STG);
    float* q2s = reinterpret_cast<float*>(smem + OFF_Q2);        // [TM]
    float* k2s = reinterpret_cast<float*>(smem + OFF_K2);        // [TN]
    float* kpart = reinterpret_cast<float*>(smem + OFF_KP);      // [8][TN]

    const int tid = threadIdx.x;
    const int lane = tid & 31;
    const int wid = tid >> 5;

    const int bh = blockIdx.z;
    const int i0 = blockIdx.y * TM;
    const int j0 = blockIdx.x * TN;

    // ---- Q load: 256 rows; 2 rows per warp-inst (16 lanes x float4). ----
    {
        const int hi = lane >> 4;
        const int seg2 = lane & 15;
#pragma unroll
        for (int p = 0; p < 16; p++) {
            const int r = wid * 2 + hi + p * 16;
            const float* qrow = q + ((size_t)bh * LQ + (size_t)(i0 + r)) * DDIM;
            float4 v = *reinterpret_cast<const float4*>(qrow + seg2 * 4);
            float s = v.x * v.x + v.y * v.y + v.z * v.z + v.w * v.w;
            s += __shfl_down_sync(0xffffffffu, s, 8, 16);
            s += __shfl_down_sync(0xffffffffu, s, 4, 16);
            s += __shfl_down_sync(0xffffffffu, s, 2, 16);
            s += __shfl_down_sync(0xffffffffu, s, 1, 16);
            if (seg2 == 0) q2s[r] = s;
            __half2 h01 = __floats2half2_rn(v.x, v.y);
            __half2 h23 = __floats2half2_rn(v.z, v.w);
            uint2 u;
            u.x = *reinterpret_cast<uint32_t*>(&h01);
            u.y = *reinterpret_cast<uint32_t*>(&h23);
            *reinterpret_cast<uint2*>(&Qs[r * QROW + seg2 * 4]) = u;
        }
    }

    // ---- K load: 256 cols (two 128-col halves); exact fp32 k2 partials. ----
#pragma unroll
    for (int jt = 0; jt < 2; jt++) {
        const float* kb = k + (size_t)bh * DDIM * LK + (size_t)(j0 + jt * SUB) + lane * 4;
        float4 ksum = make_float4(0.f, 0.f, 0.f, 0.f);
#pragma unroll
        for (int p = 0; p < 8; p++) {
            const int c = wid + p * 8;
            float4 v = *reinterpret_cast<const float4*>(kb + (size_t)c * LK);
            ksum.x += v.x * v.x; ksum.y += v.y * v.y;
            ksum.z += v.z * v.z; ksum.w += v.w * v.w;
            __half2 h01 = __floats2half2_rn(v.x, v.y);
            __half2 h23 = __floats2half2_rn(v.z, v.w);
            uint2 u;
            u.x = *reinterpret_cast<uint32_t*>(&h01);
            u.y = *reinterpret_cast<uint32_t*>(&h23);
            *reinterpret_cast<uint2*>(&Ks[c * KROW + jt * SUB + lane * 4]) = u;
        }
        *reinterpret_cast<float4*>(&kpart[wid * TN + jt * SUB + lane * 4]) = ksum;
    }
    __syncthreads();

    // ---- k2 reduce: all 256 threads, exact fp32. ----
    {
        float s = 0.0f;
#pragma unroll
        for (int w = 0; w < 8; w++) s += kpart[w * TN + tid];
        k2s[tid] = s;
    }
    __syncthreads();
    // -------- no CTA-wide barriers below this line --------

    const int wm = wid & 3;
    const int wn = wid >> 2;
    const int mbase = wm * 32;
    const int nbase = wn * 64;
    const int g = lane >> 3;      // ldmatrix quadrant
    const int lr = lane & 7;      // ldmatrix row

    uint32_t* stgW = stgall + wid * 4 * SWORDS;   // warp-private stage (288 words)
    // writer roles
    const int gq = lane >> 2;
    const int tq = lane & 3;
    const int sw = gq >> 1;       // writer super-row
    const int e0 = gq & 1;        // writer col parity / row parity
    // reader roles
    const int sr = lane >> 3;     // reader super-row (0..3)
    const int j8 = lane & 7;      // reader col chunk

#pragma unroll 1
    for (int it = 0; it < 2; it++) {
#pragma unroll 1
        for (int jt = 0; jt < 2; jt++) {
            float acc[2][8][4];
#pragma unroll
            for (int mm = 0; mm < 2; mm++)
#pragma unroll
                for (int nn = 0; nn < 8; nn++)
#pragma unroll
                    for (int r = 0; r < 4; r++)
                        acc[mm][nn][r] = 0.0f;

            // ---- Mainloop (per-warp structure identical to R5/R9). ----
#pragma unroll
            for (int ks = 0; ks < 4; ks++) {
                uint32_t A[2][4];
#pragma unroll
                for (int mm = 0; mm < 2; mm++) {
                    uint32_t addr = (uint32_t)__cvta_generic_to_shared(
                        &Qs[(it * SUB + mbase + mm * 16 + (g & 1) * 8 + lr) * QROW
                            + ks * 16 + (g >> 1) * 8]);
                    ldmatrix_x4(A[mm], addr);
                }
#pragma unroll
                for (int e = 0; e < 4; e++) {
                    uint32_t B[4];
                    uint32_t addr = (uint32_t)__cvta_generic_to_shared(
                        &Ks[(ks * 16 + (g & 1) * 8 + lr) * KROW
                            + jt * SUB + nbase + e * 16 + (g >> 1) * 8]);
                    ldmatrix_x4_trans(B, addr);
                    mma16816(acc[0][2 * e],     A[0], B[0], B[1]);
                    mma16816(acc[1][2 * e],     A[1], B[0], B[1]);
                    mma16816(acc[0][2 * e + 1], A[0], B[2], B[3]);
                    mma16816(acc[1][2 * e + 1], A[1], B[2], B[3]);
                }
            }

            // ---- fp16 interleaved-stage epilogue. ----
            // preload k2 (fixed per lane) and q2 (2 rows per slab x 4 slabs)
            float4 k2A = *reinterpret_cast<const float4*>(
                &k2s[jt * SUB + nbase + j8 * 4]);
            float4 k2B = *reinterpret_cast<const float4*>(
                &k2s[jt * SUB + nbase + 32 + j8 * 4]);
            float q2r[8];
#pragma unroll
            for (int mm = 0; mm < 2; mm++)
#pragma unroll
                for (int h = 0; h < 2; h++)
#pragma unroll
                    for (int p = 0; p < 2; p++)
                        q2r[mm * 4 + h * 2 + p] =
                            q2s[it * SUB + mbase + mm * 16 + h * 8 + 2 * sr + p];

#pragma unroll
            for (int mm = 0; mm < 2; mm++) {
#pragma unroll
                for (int h = 0; h < 2; h++) {
                    __syncwarp();
                    // writer: pack (-2*acc) as half2, exchange row-pair via shfl,
                    // merge to (rowEven, rowOdd) half2 for own col parity, STS.32.
#pragma unroll
                    for (int nn = 0; nn < 8; nn++) {
                        __half2 hp = __floats2half2_rn(-2.0f * acc[mm][nn][2 * h],
                                                       -2.0f * acc[mm][nn][2 * h + 1]);
                        uint32_t own = *reinterpret_cast<uint32_t*>(&hp);
                        uint32_t rp = __shfl_xor_sync(0xffffffffu, own, 4);
                        uint32_t mrg = e0 ? ((rp >> 16) | (own & 0xFFFF0000u))
                                          : ((own & 0x0000FFFFu) | (rp << 16));
                        stgW[sw * SWORDS + 8 * nn + 2 * tq + e0] = mrg;
                    }
                    __syncwarp();
                    // reader: 2x LDS.128 -> cvt -> 4x STG.128 (4 rows x 128B dense)
#pragma unroll
                    for (int L = 0; L < 2; L++) {
                        uint4 w = *reinterpret_cast<const uint4*>(
                            &stgW[sr * SWORDS + (j8 + 8 * L) * 4]);
                        float2 c0 = __half22float2(*reinterpret_cast<__half2*>(&w.x));
                        float2 c1 = __half22float2(*reinterpret_cast<__half2*>(&w.y));
                        float2 c2 = __half22float2(*reinterpret_cast<__half2*>(&w.z));
                        float2 c3 = __half22float2(*reinterpret_cast<__half2*>(&w.w));
                        const float4 k2v = L ? k2B : k2A;
                        const float q2e = q2r[mm * 4 + h * 2 + 0];
                        const float q2o = q2r[mm * 4 + h * 2 + 1];
                        float4 oe, oo;
                        oe.x = q2e + k2v.x + c0.x;
                        oe.y = q2e + k2v.y + c1.x;
                        oe.z = q2e + k2v.z + c2.x;
                        oe.w = q2e + k2v.w + c3.x;
                        oo.x = q2o + k2v.x + c0.y;
                        oo.y = q2o + k2v.y + c1.y;
                        oo.z = q2o + k2v.z + c2.y;
                        oo.w = q2o + k2v.w + c3.y;
                        const size_t rbase = (size_t)bh * LQ +
                            (size_t)(i0 + it * SUB + mbase + mm * 16 + h * 8 + 2 * sr);
                        const int cg = j0 + jt * SUB + nbase + 32 * L + 4 * j8;
                        *reinterpret_cast<float4*>(out + rbase * LK + cg) = oe;
                        *reinterpret_cast<float4*>(out + (rbase + 1) * LK + cg) = oo;
                    }
                }
            }
        }
    }
}

// ---------------- Launch ----------------

extern "C" void kernel_launch(void* const* d_in, const int* in_sizes, int n_in,
                              void* d_out, int out_size) {
    const float* q = (const float*)d_in[0];   // [4,8,2048,64]
    const float* k = (const float*)d_in[1];   // [4,8,64,2048]
    float* out = (float*)d_out;               // [4,8,2048,2048]
    (void)in_sizes; (void)n_in; (void)out_size;

    cudaFuncSetAttribute(subgauss_kernel,
                         cudaFuncAttributeMaxDynamicSharedMemorySize, SMEM_TOTAL);

    dim3 grid(LK / TN, LQ / TM, 32);  // 8 x 8 x 32
    subgauss_kernel<<<grid, THREADS, SMEM_TOTAL>>>(q, k, out);
}

// round 11
// speedup vs baseline: 1.7961x; 1.0590x over previous
#include <cuda_runtime.h>
#include <cuda_fp16.h>
#include <cstdint>

// ============================================================================
// SubtractionGaussian: out[b,h,i,j] = ||q_i||^2 + ||k_j||^2 - 2 q_i . k_j
// B*H = 32, Lq = Lk = 2048, D = 64, fp32 in/out.
//
// R11: fp16 accumulators (m16n8k16.f16) -> acc 32 regs -> 3 CTAs/SM (24 warps),
//      K carries -2 so acc == stage payload (writer = shfl + prmt + STS only).
//      TM=128 x TN=256 per CTA (Q reused across 2 col-halves), smem 63KB.
// ============================================================================

#define LQ 2048
#define LK 2048
#define DDIM 64
#define TM 128
#define TN 256
#define SUBN 128
#define THREADS 256

#define QROW 72         // halfs per Qs row (9 granules == 1 mod 8 -> ldmatrix conflict-free)
#define KROW 264        // halfs per Ks row (33 granules == 1 mod 8 -> conflict-free)
#define SWORDS 72       // stage super-row pitch in words (== 8 mod 32 -> STS conflict-free)

// dynamic smem layout (bytes)
#define OFF_QS   0                        // 128*72*2  = 18432
#define OFF_KS   18432                    // 64*264*2  = 33792
#define OFF_STG  52224                    // 8 warps * 4*72*4 = 9216 (kpart aliases here)
#define OFF_Q2   61440                    // 128*4     = 512
#define OFF_K2   61952                    // 256*4     = 1024
#define SMEM_TOTAL 62976

// f16-accum MMA: D,C are 2 regs of half2. Chained D=C.
__device__ __forceinline__ void mma16816_f16(uint32_t* d, const uint32_t* a,
                                             uint32_t b0, uint32_t b1) {
    asm volatile(
        "mma.sync.aligned.m16n8k16.row.col.f16.f16.f16.f16 "
        "{%0,%1}, {%2,%3,%4,%5}, {%6,%7}, {%0,%1};"
        : "+r"(d[0]), "+r"(d[1])
        : "r"(a[0]), "r"(a[1]), "r"(a[2]), "r"(a[3]), "r"(b0), "r"(b1));
}

__device__ __forceinline__ void ldmatrix_x4(uint32_t* r, uint32_t addr) {
    asm volatile("ldmatrix.sync.aligned.m8n8.x4.shared.b16 {%0,%1,%2,%3}, [%4];"
                 : "=r"(r[0]), "=r"(r[1]), "=r"(r[2]), "=r"(r[3]) : "r"(addr));
}

__device__ __forceinline__ void ldmatrix_x4_trans(uint32_t* r, uint32_t addr) {
    asm volatile("ldmatrix.sync.aligned.m8n8.x4.trans.shared.b16 {%0,%1,%2,%3}, [%4];"
                 : "=r"(r[0]), "=r"(r[1]), "=r"(r[2]), "=r"(r[3]) : "r"(addr));
}

__global__ void __launch_bounds__(THREADS, 3)
subgauss_kernel(const float* __restrict__ q,   // [BH, Lq, D]
                const float* __restrict__ k,   // [BH, D, Lk]
                float* __restrict__ out)       // [BH, Lq, Lk]
{
    extern __shared__ __align__(16) char smem[];
    __half* Qs = reinterpret_cast<__half*>(smem + OFF_QS);       // [TM][QROW]
    __half* Ks = reinterpret_cast<__half*>(smem + OFF_KS);       // [DDIM][KROW], holds -2k
    uint32_t* stgall = reinterpret_cast<uint32_t*>(smem + OFF_STG);
    float* kpart = reinterpret_cast<float*>(smem + OFF_STG);     // alias: dead before stage use
    float* q2s = reinterpret_cast<float*>(smem + OFF_Q2);        // [TM]
    float* k2s = reinterpret_cast<float*>(smem + OFF_K2);        // [TN]

    const int tid = threadIdx.x;
    const int lane = tid & 31;
    const int wid = tid >> 5;

    const int bh = blockIdx.z;
    const int i0 = blockIdx.y * TM;
    const int j0 = blockIdx.x * TN;

    // ---- Q load: 128 rows; 2 rows per warp-inst (16 lanes x float4). ----
    {
        const int hi = lane >> 4;
        const int seg2 = lane & 15;
#pragma unroll
        for (int p = 0; p < 8; p++) {
            const int r = wid * 2 + hi + p * 16;
            const float* qrow = q + ((size_t)bh * LQ + (size_t)(i0 + r)) * DDIM;
            float4 v = *reinterpret_cast<const float4*>(qrow + seg2 * 4);
            float s = v.x * v.x + v.y * v.y + v.z * v.z + v.w * v.w;
            s += __shfl_down_sync(0xffffffffu, s, 8, 16);
            s += __shfl_down_sync(0xffffffffu, s, 4, 16);
            s += __shfl_down_sync(0xffffffffu, s, 2, 16);
            s += __shfl_down_sync(0xffffffffu, s, 1, 16);
            if (seg2 == 0) q2s[r] = s;
            __half2 h01 = __floats2half2_rn(v.x, v.y);
            __half2 h23 = __floats2half2_rn(v.z, v.w);
            uint2 u;
            u.x = *reinterpret_cast<uint32_t*>(&h01);
            u.y = *reinterpret_cast<uint32_t*>(&h23);
            *reinterpret_cast<uint2*>(&Qs[r * QROW + seg2 * 4]) = u;
        }
    }

    // ---- K load: 256 cols (two halves); Ks holds -2k; exact fp32 k2 partials. ----
#pragma unroll
    for (int jt = 0; jt < 2; jt++) {
        const float* kb = k + (size_t)bh * DDIM * LK + (size_t)(j0 + jt * SUBN) + lane * 4;
        float4 ksum = make_float4(0.f, 0.f, 0.f, 0.f);
#pragma unroll
        for (int p = 0; p < 8; p++) {
            const int c = wid + p * 8;
            float4 v = *reinterpret_cast<const float4*>(kb + (size_t)c * LK);
            ksum.x += v.x * v.x; ksum.y += v.y * v.y;
            ksum.z += v.z * v.z; ksum.w += v.w * v.w;
            __half2 h01 = __floats2half2_rn(-2.0f * v.x, -2.0f * v.y);
            __half2 h23 = __floats2half2_rn(-2.0f * v.z, -2.0f * v.w);
            uint2 u;
            u.x = *reinterpret_cast<uint32_t*>(&h01);
            u.y = *reinterpret_cast<uint32_t*>(&h23);
            *reinterpret_cast<uint2*>(&Ks[c * KROW + jt * SUBN + lane * 4]) = u;
        }
        *reinterpret_cast<float4*>(&kpart[wid * TN + jt * SUBN + lane * 4]) = ksum;
    }
    __syncthreads();

    // ---- k2 reduce: 256 threads, exact fp32 (kpart region dies here). ----
    {
        float s = 0.0f;
#pragma unroll
        for (int w = 0; w < 8; w++) s += kpart[w * TN + tid];
        k2s[tid] = s;
    }
    __syncthreads();
    // -------- no CTA-wide barriers below this line --------

    const int wm = wid & 3;
    const int wn = wid >> 2;
    const int mbase = wm * 32;
    const int nbase = wn * 64;
    const int g = lane >> 3;      // ldmatrix quadrant
    const int lr = lane & 7;      // ldmatrix row

    uint32_t* stgW = stgall + wid * 4 * SWORDS;   // warp-private stage
    // writer roles
    const int tq = lane & 3;
    const int sw = (lane >> 2) >> 1;     // super-row
    const int e0 = (lane >> 2) & 1;      // row parity
    const uint32_t psel = e0 ? 0x3276u : 0x5410u;
    // reader roles
    const int sr = lane >> 3;
    const int j8 = lane & 7;

    // q2 rows fixed across jt: preload 8 values (mm,h,parity)
    float q2r[8];
#pragma unroll
    for (int mm = 0; mm < 2; mm++)
#pragma unroll
        for (int h = 0; h < 2; h++)
#pragma unroll
            for (int p = 0; p < 2; p++)
                q2r[mm * 4 + h * 2 + p] = q2s[mbase + mm * 16 + h * 8 + 2 * sr + p];

#pragma unroll 1
    for (int jt = 0; jt < 2; jt++) {
        uint32_t acc[2][8][2];
#pragma unroll
        for (int mm = 0; mm < 2; mm++)
#pragma unroll
            for (int nn = 0; nn < 8; nn++) {
                acc[mm][nn][0] = 0u;
                acc[mm][nn][1] = 0u;
            }

        // ---- Mainloop: fp16 accumulate; acc = -2*q.k (K pre-scaled). ----
#pragma unroll
        for (int ks = 0; ks < 4; ks++) {
            uint32_t A[2][4];
#pragma unroll
            for (int mm = 0; mm < 2; mm++) {
                uint32_t addr = (uint32_t)__cvta_generic_to_shared(
                    &Qs[(mbase + mm * 16 + (g & 1) * 8 + lr) * QROW
                        + ks * 16 + (g >> 1) * 8]);
                ldmatrix_x4(A[mm], addr);
            }
#pragma unroll
            for (int e = 0; e < 4; e++) {
                uint32_t B[4];
                uint32_t addr = (uint32_t)__cvta_generic_to_shared(
                    &Ks[(ks * 16 + (g & 1) * 8 + lr) * KROW
                        + jt * SUBN + nbase + e * 16 + (g >> 1) * 8]);
                ldmatrix_x4_trans(B, addr);
                mma16816_f16(acc[0][2 * e],     A[0], B[0], B[1]);
                mma16816_f16(acc[1][2 * e],     A[1], B[0], B[1]);
                mma16816_f16(acc[0][2 * e + 1], A[0], B[2], B[3]);
                mma16816_f16(acc[1][2 * e + 1], A[1], B[2], B[3]);
            }
        }

        // ---- Epilogue: acc word IS the stage payload (no cvt, no mul). ----
        float4 k2A = *reinterpret_cast<const float4*>(&k2s[jt * SUBN + nbase + j8 * 4]);
        float4 k2B = *reinterpret_cast<const float4*>(&k2s[jt * SUBN + nbase + 32 + j8 * 4]);

#pragma unroll
        for (int mm = 0; mm < 2; mm++) {
#pragma unroll
            for (int h = 0; h < 2; h++) {
                __syncwarp();
                // writer: row-pair interleave via shfl.xor(4) + PRMT, STS.32
#pragma unroll
                for (int nn = 0; nn < 8; nn++) {
                    uint32_t own = acc[mm][nn][h];
                    uint32_t rp = __shfl_xor_sync(0xffffffffu, own, 4);
                    uint32_t mrg = __byte_perm(own, rp, psel);
                    stgW[sw * SWORDS + 8 * nn + 2 * tq + e0] = mrg;
                }
                __syncwarp();
                // reader: 2x LDS.128 -> cvt -> 4x STG.128 (4 rows x 128B dense)
#pragma unroll
                for (int L = 0; L < 2; L++) {
                    uint4 w = *reinterpret_cast<const uint4*>(
                        &stgW[sr * SWORDS + (j8 + 8 * L) * 4]);
                    float2 c0 = __half22float2(*reinterpret_cast<__half2*>(&w.x));
                    float2 c1 = __half22float2(*reinterpret_cast<__half2*>(&w.y));
                    float2 c2 = __half22float2(*reinterpret_cast<__half2*>(&w.z));
                    float2 c3 = __half22float2(*reinterpret_cast<__half2*>(&w.w));
                    const float4 k2v = L ? k2B : k2A;
                    const float q2e = q2r[mm * 4 + h * 2 + 0];
                    const float q2o = q2r[mm * 4 + h * 2 + 1];
                    float4 oe, oo;
                    oe.x = q2e + k2v.x + c0.x;
                    oe.y = q2e + k2v.y + c1.x;
                    oe.z = q2e + k2v.z + c2.x;
                    oe.w = q2e + k2v.w + c3.x;
                    oo.x = q2o + k2v.x + c0.y;
                    oo.y = q2o + k2v.y + c1.y;
                    oo.z = q2o + k2v.z + c2.y;
                    oo.w = q2o + k2v.w + c3.y;
                    const size_t rbase = (size_t)bh * LQ +
                        (size_t)(i0 + mbase + mm * 16 + h * 8 + 2 * sr);
                    const int cg = j0 + jt * SUBN + nbase + 32 * L + 4 * j8;
                    *reinterpret_cast<float4*>(out + rbase * LK + cg) = oe;
                    *reinterpret_cast<float4*>(out + (rbase + 1) * LK + cg) = oo;
                }
            }
        }
    }
}

// ---------------- Launch ----------------

extern "C" void kernel_launch(void* const* d_in, const int* in_sizes, int n_in,
                              void* d_out, int out_size) {
    const float* q = (const float*)d_in[0];   // [4,8,2048,64]
    const float* k = (const float*)d_in[1];   // [4,8,64,2048]
    float* out = (float*)d_out;               // [4,8,2048,2048]
    (void)in_sizes; (void)n_in; (void)out_size;

    cudaFuncSetAttribute(subgauss_kernel,
                         cudaFuncAttributeMaxDynamicSharedMemorySize, SMEM_TOTAL);

    dim3 grid(LK / TN, LQ / TM, 32);  // 8 x 16 x 32
    subgauss_kernel<<<grid, THREADS, SMEM_TOTAL>>>(q, k, out);
}